// round 10
// baseline (speedup 1.0000x reference)
#include <cuda_runtime.h>
#include <cstdint>

#define N_NODES   50000
#define N_EDGES   800000
#define IN_DIM    128     // 4*MUL
#define W_DIM     160     // 5*MUL
#define OUT_DIM   224     // 7*MUL
#define MUL       32
#define CAP       64      // bucket slots per node (Poisson(16): P(deg>64) ~ 1e-20)
#define NCHUNK    32      // CAP/2 chunks of 2 edges

#define INV_SQRT3f 0.57735026918962576451f
#define INV_SQRT2f 0.70710678118654752440f

// scratch
__device__ int  g_cnt[N_NODES];
__device__ int2 g_bk[(size_t)N_NODES * CAP];   // {edge_id, src} — 25.6 MB

__device__ __forceinline__ void red4(float* addr, float a, float b, float c, float d) {
    asm volatile("red.global.add.v4.f32 [%0], {%1, %2, %3, %4};"
                 :: "l"(addr), "f"(a), "f"(b), "f"(c), "f"(d)
                 : "memory");
}

__device__ __forceinline__ float4 ldcs4(const float4* p) { return __ldcs(p); }

// k0: zero output + per-node counters
__global__ void zero_kernel(float4* __restrict__ out, int n4) {
    int i = blockIdx.x * blockDim.x + threadIdx.x;
    int stride = gridDim.x * blockDim.x;
    float4 z = make_float4(0.f, 0.f, 0.f, 0.f);
    for (int k = i; k < n4; k += stride) out[k] = z;
    for (int k = i; k < N_NODES; k += stride) g_cnt[k] = 0;
}

// k1: scatter (edge_id, src) into dst buckets
__global__ __launch_bounds__(256)
void scatter_kernel(const int* __restrict__ ei) {
    int e = blockIdx.x * blockDim.x + threadIdx.x;
    if (e >= N_EDGES) return;
    int2 se = __ldcs(((const int2*)ei) + e);
    int slot = atomicAdd(&g_cnt[se.y], 1);
    if (slot < CAP) g_bk[(size_t)se.y * CAP + slot] = make_int2(e, se.x);
}

// k2: one 8-thread group per (node, chunk of 2 edges). Thread t owns channels [4t,4t+4).
// Both edges' loads are straight-line & independent (front-batched); edge1 is
// neutralized via m1=0 when the chunk has only one edge. 7 red4 per CHUNK (not per edge).
__global__ __launch_bounds__(256, 4)
void gather_kernel(const float* __restrict__ nf,   // [N_NODES, 128]
                   const float* __restrict__ ang,  // [N_EDGES, 4]
                   const float* __restrict__ tw,   // [N_EDGES, 160]
                   float* __restrict__ out)        // [N_NODES, 224]
{
    int gid = blockIdx.x * blockDim.x + threadIdx.x;
    int g = gid >> 3;
    int t = gid & 7;
    int node  = g >> 5;       // g / NCHUNK
    int chunk = g & 31;       // g % NCHUNK
    if (node >= N_NODES) return;

    int deg = g_cnt[node];
    if (deg > CAP) deg = CAP;
    int base = chunk * 2;
    if (base >= deg) return;

    // two bucket entries: {e0, s0, e1, s1}; chunk*2 int2 = 16B aligned
    int4 bk = *(const int4*)(g_bk + (size_t)node * CAP + base);
    bool has2 = (base + 1 < deg);
    int e0 = bk.x, s0 = bk.y;
    int e1 = has2 ? bk.z : bk.x;
    int s1 = has2 ? bk.w : bk.y;
    float m1 = has2 ? 1.0f : 0.0f;

    // ---- independent loads for both edges (batchable) ----
    float4 ya = ldcs4(((const float4*)ang) + e0);
    float4 yb = ldcs4(((const float4*)ang) + e1);

    const float4* hp0 = (const float4*)(nf + (long long)s0 * IN_DIM);
    const float4* hp1 = (const float4*)(nf + (long long)s1 * IN_DIM);
    float4 a_h0 = __ldg(hp0 + t);
    float4 a_ha = __ldg(hp0 + 8  + t);
    float4 a_hb = __ldg(hp0 + 16 + t);
    float4 a_hc = __ldg(hp0 + 24 + t);
    float4 b_h0 = __ldg(hp1 + t);
    float4 b_ha = __ldg(hp1 + 8  + t);
    float4 b_hb = __ldg(hp1 + 16 + t);
    float4 b_hc = __ldg(hp1 + 24 + t);

    const float4* wp0 = (const float4*)(tw + (long long)e0 * W_DIM);
    const float4* wp1 = (const float4*)(tw + (long long)e1 * W_DIM);
    float4 a_w0 = ldcs4(wp0 + t);
    float4 a_w1 = ldcs4(wp0 + 8  + t);
    float4 a_w2 = ldcs4(wp0 + 16 + t);
    float4 a_w3 = ldcs4(wp0 + 24 + t);
    float4 a_w4 = ldcs4(wp0 + 32 + t);
    float4 b_w0 = ldcs4(wp1 + t);
    float4 b_w1 = ldcs4(wp1 + 8  + t);
    float4 b_w2 = ldcs4(wp1 + 16 + t);
    float4 b_w3 = ldcs4(wp1 + 24 + t);
    float4 b_w4 = ldcs4(wp1 + 32 + t);

    float r0[4], o1o0[4], o1o1[4], o1o2[4], o1e0[4], o1e1[4], o1e2[4];

    {   // edge 0 contribution (initializes accumulators)
        const float y0 = ya.x, y1x = ya.y, y1y = ya.z, y1z = ya.w;
        const float* h0 = (const float*)&a_h0;
        const float* ha = (const float*)&a_ha;
        const float* hb = (const float*)&a_hb;
        const float* hc = (const float*)&a_hc;
        const float* w0 = (const float*)&a_w0;
        const float* w1 = (const float*)&a_w1;
        const float* w2 = (const float*)&a_w2;
        const float* w3 = (const float*)&a_w3;
        const float* w4 = (const float*)&a_w4;
        #pragma unroll
        for (int j = 0; j < 4; j++) {
            float H0 = h0[j];
            float A = ha[j], B = hb[j], C = hc[j];
            float dot = A * y1x + B * y1y + C * y1z;
            r0[j]   = w0[j] * H0 * y0 + w3[j] * (INV_SQRT3f * dot);
            o1o0[j] = w1[j] * H0 * y1x + w2[j] * A * y0;
            o1o1[j] = w1[j] * H0 * y1y + w2[j] * B * y0;
            o1o2[j] = w1[j] * H0 * y1z + w2[j] * C * y0;
            float cr0 = B * y1z - C * y1y;
            float cr1 = C * y1x - A * y1z;
            float cr2 = A * y1y - B * y1x;
            o1e0[j] = w4[j] * (INV_SQRT2f * cr0);
            o1e1[j] = w4[j] * (INV_SQRT2f * cr1);
            o1e2[j] = w4[j] * (INV_SQRT2f * cr2);
        }
    }
    {   // edge 1 contribution, scaled by m1 (0 if absent)
        const float y0 = yb.x, y1x = yb.y, y1y = yb.z, y1z = yb.w;
        const float* h0 = (const float*)&b_h0;
        const float* ha = (const float*)&b_ha;
        const float* hb = (const float*)&b_hb;
        const float* hc = (const float*)&b_hc;
        const float* w0 = (const float*)&b_w0;
        const float* w1 = (const float*)&b_w1;
        const float* w2 = (const float*)&b_w2;
        const float* w3 = (const float*)&b_w3;
        const float* w4 = (const float*)&b_w4;
        #pragma unroll
        for (int j = 0; j < 4; j++) {
            float H0 = h0[j];
            float A = ha[j], B = hb[j], C = hc[j];
            float dot = A * y1x + B * y1y + C * y1z;
            float W0 = w0[j] * m1, W1 = w1[j] * m1, W2 = w2[j] * m1;
            float W3 = w3[j] * m1, W4 = w4[j] * m1;
            r0[j]   += W0 * H0 * y0 + W3 * (INV_SQRT3f * dot);
            o1o0[j] += W1 * H0 * y1x + W2 * A * y0;
            o1o1[j] += W1 * H0 * y1y + W2 * B * y0;
            o1o2[j] += W1 * H0 * y1z + W2 * C * y0;
            float cr0 = B * y1z - C * y1y;
            float cr1 = C * y1x - A * y1z;
            float cr2 = A * y1y - B * y1x;
            o1e0[j] += W4 * (INV_SQRT2f * cr0);
            o1e1[j] += W4 * (INV_SQRT2f * cr1);
            o1e2[j] += W4 * (INV_SQRT2f * cr2);
        }
    }

    float* op = out + (long long)node * OUT_DIM + 4 * t;
    red4(op,             r0[0],   r0[1],   r0[2],   r0[3]);
    red4(op + MUL,       o1o0[0], o1o0[1], o1o0[2], o1o0[3]);
    red4(op + 2 * MUL,   o1o1[0], o1o1[1], o1o1[2], o1o1[3]);
    red4(op + 3 * MUL,   o1o2[0], o1o2[1], o1o2[2], o1o2[3]);
    red4(op + 4 * MUL,   o1e0[0], o1e0[1], o1e0[2], o1e0[3]);
    red4(op + 5 * MUL,   o1e1[0], o1e1[1], o1e1[2], o1e1[3]);
    red4(op + 6 * MUL,   o1e2[0], o1e2[1], o1e2[2], o1e2[3]);
}

extern "C" void kernel_launch(void* const* d_in, const int* in_sizes, int n_in,
                              void* d_out, int out_size) {
    const float* nf  = (const float*)d_in[0];   // node_features
    const float* ang = (const float*)d_in[1];   // edge_angular
    const int*   ei  = (const int*)d_in[2];     // edge_index (int32)
    const float* tw  = (const float*)d_in[3];   // tp_weights
    float* out = (float*)d_out;

    // k0: zero output + counters
    int n4 = out_size / 4;
    int zgrid = (n4 + 255) / 256;
    if (zgrid > 2368) zgrid = 2368;
    zero_kernel<<<zgrid, 256>>>((float4*)out, n4);

    // k1: scatter edges into dst buckets
    scatter_kernel<<<(N_EDGES + 255) / 256, 256>>>(ei);

    // k2: gather — N_NODES * NCHUNK groups * 8 threads
    long long total = (long long)N_NODES * NCHUNK * 8;
    int grid = (int)((total + 255) / 256);
    gather_kernel<<<grid, 256>>>(nf, ang, tw, out);
}

// round 11
// speedup vs baseline: 1.2034x; 1.2034x over previous
#include <cuda_runtime.h>
#include <cstdint>

#define N_NODES   50000
#define N_EDGES   800000
#define IN_DIM    128     // 4*MUL
#define W_DIM     160     // 5*MUL
#define OUT_DIM   224     // 7*MUL
#define MUL       32
#define EDGES_PER_CTA 32  // 256 threads / 8 threads-per-edge

#define INV_SQRT3f 0.57735026918962576451f
#define INV_SQRT2f 0.70710678118654752440f

__device__ __forceinline__ float4 ldcs4(const float4* p) { return __ldcs(p); }

__device__ __forceinline__ uint32_t smem_u32(const void* p) {
    uint32_t a;
    asm("{ .reg .u64 t; cvta.to.shared.u64 t, %1; cvt.u32.u64 %0, t; }"
        : "=r"(a) : "l"(p));
    return a;
}

__global__ void zero_out_kernel(float4* __restrict__ out, int n4) {
    int i = blockIdx.x * blockDim.x + threadIdx.x;
    int stride = gridDim.x * blockDim.x;
    float4 z = make_float4(0.f, 0.f, 0.f, 0.f);
    for (; i < n4; i += stride) out[i] = z;
}

// One edge per 8 threads; 32 edges per CTA. Compute into SMEM, then per-edge
// cp.reduce.async.bulk (TMA-side add) to the dst row — no LSU atomics.
__global__ __launch_bounds__(256, 4)
void convtp_kernel(const float* __restrict__ nf,   // [N_NODES, 128]
                   const float* __restrict__ ang,  // [N_EDGES, 4]
                   const int* __restrict__ ei,     // [N_EDGES, 2] int32
                   const float* __restrict__ tw,   // [N_EDGES, 160]
                   float* __restrict__ out)        // [N_NODES, 224]
{
    __shared__ float buf[EDGES_PER_CTA * OUT_DIM];  // 28672 B
    __shared__ int   dsts[EDGES_PER_CTA];

    int tid = threadIdx.x;
    int ein = tid >> 3;                    // edge index within CTA (0..31)
    int t   = tid & 7;                     // channel-group owner (0..7)
    int e   = blockIdx.x * EDGES_PER_CTA + ein;   // grid sized exactly: always valid

    // edge index — single-use stream, evict-first
    int2 se = __ldcs(((const int2*)ei) + e);
    int src = se.x;
    if (t == 0) dsts[ein] = se.y;

    // angular — single-use stream, evict-first
    float4 y = ldcs4(((const float4*)ang) + e);

    // gather node features: read-only cached (R3-proven best)
    const float4* hp = (const float4*)(nf + (long long)src * IN_DIM);
    float4 h0v = __ldg(hp + t);
    float4 hav = __ldg(hp + 8  + t);
    float4 hbv = __ldg(hp + 16 + t);
    float4 hcv = __ldg(hp + 24 + t);

    // weights — 512MB single-use stream, evict-first
    const float4* wp = (const float4*)(tw + (long long)e * W_DIM);
    float4 w0v = ldcs4(wp + t);
    float4 w1v = ldcs4(wp + 8  + t);
    float4 w2v = ldcs4(wp + 16 + t);
    float4 w3v = ldcs4(wp + 24 + t);
    float4 w4v = ldcs4(wp + 32 + t);

    const float y0  = y.x;
    const float y1x = y.y, y1y = y.z, y1z = y.w;

    const float* h0 = (const float*)&h0v;
    const float* ha = (const float*)&hav;
    const float* hb = (const float*)&hbv;
    const float* hc = (const float*)&hcv;
    const float* w0 = (const float*)&w0v;
    const float* w1 = (const float*)&w1v;
    const float* w2 = (const float*)&w2v;
    const float* w3 = (const float*)&w3v;
    const float* w4 = (const float*)&w4v;

    float r0[4], o1o0[4], o1o1[4], o1o2[4], o1e0[4], o1e1[4], o1e2[4];

    #pragma unroll
    for (int j = 0; j < 4; j++) {
        float H0 = h0[j];
        float A = ha[j], B = hb[j], C = hc[j];   // h1[0..2]
        float dot = A * y1x + B * y1y + C * y1z;

        r0[j]   = w0[j] * H0 * y0 + w3[j] * (INV_SQRT3f * dot);

        o1o0[j] = w1[j] * H0 * y1x + w2[j] * A * y0;
        o1o1[j] = w1[j] * H0 * y1y + w2[j] * B * y0;
        o1o2[j] = w1[j] * H0 * y1z + w2[j] * C * y0;

        float cr0 = B * y1z - C * y1y;
        float cr1 = C * y1x - A * y1z;
        float cr2 = A * y1y - B * y1x;
        o1e0[j] = w4[j] * (INV_SQRT2f * cr0);
        o1e1[j] = w4[j] * (INV_SQRT2f * cr1);
        o1e2[j] = w4[j] * (INV_SQRT2f * cr2);
    }

    // write message into SMEM (lanes 0-7 of a warp cover one edge's contiguous
    // 128B per segment -> conflict-free STS.128 phases)
    float4* bp = (float4*)(buf + ein * OUT_DIM);   // 14 float4 per edge row... (56 actually)
    bp[t]          = make_float4(r0[0],   r0[1],   r0[2],   r0[3]);
    bp[8  + t]     = make_float4(o1o0[0], o1o0[1], o1o0[2], o1o0[3]);
    bp[16 + t]     = make_float4(o1o1[0], o1o1[1], o1o1[2], o1o1[3]);
    bp[24 + t]     = make_float4(o1o2[0], o1o2[1], o1o2[2], o1o2[3]);
    bp[32 + t]     = make_float4(o1e0[0], o1e0[1], o1e0[2], o1e0[3]);
    bp[40 + t]     = make_float4(o1e1[0], o1e1[1], o1e1[2], o1e1[3]);
    bp[48 + t]     = make_float4(o1e2[0], o1e2[1], o1e2[2], o1e2[3]);

    // make SMEM writes visible to the async proxy, then sync the CTA
    asm volatile("fence.proxy.async.shared::cta;" ::: "memory");
    __syncthreads();

    // threads 0..31 each issue one 896B bulk-reduce (add) to their edge's dst row
    if (tid < EDGES_PER_CTA) {
        uint32_t saddr = smem_u32(buf + tid * OUT_DIM);
        float* gaddr = out + (long long)dsts[tid] * OUT_DIM;
        asm volatile(
            "cp.reduce.async.bulk.global.shared::cta.bulk_group.add.f32 [%0], [%1], %2;"
            :: "l"(gaddr), "r"(saddr), "n"(OUT_DIM * 4) : "memory");
        asm volatile("cp.async.bulk.commit_group;" ::: "memory");
        asm volatile("cp.async.bulk.wait_group 0;" ::: "memory");
    }
}

extern "C" void kernel_launch(void* const* d_in, const int* in_sizes, int n_in,
                              void* d_out, int out_size) {
    const float* nf  = (const float*)d_in[0];   // node_features
    const float* ang = (const float*)d_in[1];   // edge_angular
    const int*   ei  = (const int*)d_in[2];     // edge_index (int32)
    const float* tw  = (const float*)d_in[3];   // tp_weights
    float* out = (float*)d_out;

    // zero the (poisoned) output — vectorized
    int n4 = out_size / 4;
    int zgrid = (n4 + 255) / 256;
    if (zgrid > 2368) zgrid = 2368;
    zero_out_kernel<<<zgrid, 256>>>((float4*)out, n4);

    // main kernel: 25000 CTAs, 32 edges each (exact cover of 800000 edges)
    convtp_kernel<<<N_EDGES / EDGES_PER_CTA, 256>>>(nf, ang, ei, tw, out);
}

// round 12
// speedup vs baseline: 1.2915x; 1.0732x over previous
#include <cuda_runtime.h>
#include <cstdint>

#define N_NODES   50000
#define N_EDGES   800000
#define IN_DIM    128     // 4*MUL
#define W_DIM     160     // 5*MUL
#define OUT_DIM   224     // 7*MUL
#define MUL       32
#define BLOCK     128
#define EDGES_PER_CTA (BLOCK / 8)   // 16

#define INV_SQRT3f 0.57735026918962576451f
#define INV_SQRT2f 0.70710678118654752440f

__device__ __forceinline__ float4 ldcs4(const float4* p) { return __ldcs(p); }

__device__ __forceinline__ uint32_t smem_u32(const void* p) {
    uint32_t a;
    asm("{ .reg .u64 t; cvta.to.shared.u64 t, %1; cvt.u32.u64 %0, t; }"
        : "=r"(a) : "l"(p));
    return a;
}

__global__ void zero_out_kernel(float4* __restrict__ out, int n4) {
    int i = blockIdx.x * blockDim.x + threadIdx.x;
    int stride = gridDim.x * blockDim.x;
    float4 z = make_float4(0.f, 0.f, 0.f, 0.f);
    for (; i < n4; i += stride) out[i] = z;
}

// One edge per 8 threads; 16 edges per 128-thread CTA. Compute into SMEM,
// then each warp's lanes 0/8/16/24 issue one 896B cp.reduce.async.bulk (add)
// for their own edge. NO CTA-wide sync — per-warp tails overlap.
__global__ __launch_bounds__(BLOCK)
void convtp_kernel(const float* __restrict__ nf,   // [N_NODES, 128]
                   const float* __restrict__ ang,  // [N_EDGES, 4]
                   const int* __restrict__ ei,     // [N_EDGES, 2] int32
                   const float* __restrict__ tw,   // [N_EDGES, 160]
                   float* __restrict__ out)        // [N_NODES, 224]
{
    __shared__ float buf[EDGES_PER_CTA * OUT_DIM];  // 14336 B

    int tid = threadIdx.x;
    int ein = tid >> 3;                    // edge slot within CTA (0..15)
    int t   = tid & 7;                     // channel-group owner (0..7)
    int e   = blockIdx.x * EDGES_PER_CTA + ein;   // grid is exact cover

    // edge index — single-use stream, evict-first
    int2 se = __ldcs(((const int2*)ei) + e);
    int src = se.x;
    int dst = se.y;

    // angular — single-use stream, evict-first
    float4 y = ldcs4(((const float4*)ang) + e);

    // gather node features: read-only cached (proven best)
    const float4* hp = (const float4*)(nf + (long long)src * IN_DIM);
    float4 h0v = __ldg(hp + t);
    float4 hav = __ldg(hp + 8  + t);
    float4 hbv = __ldg(hp + 16 + t);
    float4 hcv = __ldg(hp + 24 + t);

    // weights — 512MB single-use stream, evict-first
    const float4* wp = (const float4*)(tw + (long long)e * W_DIM);
    float4 w0v = ldcs4(wp + t);
    float4 w1v = ldcs4(wp + 8  + t);
    float4 w2v = ldcs4(wp + 16 + t);
    float4 w3v = ldcs4(wp + 24 + t);
    float4 w4v = ldcs4(wp + 32 + t);

    const float y0  = y.x;
    const float y1x = y.y, y1y = y.z, y1z = y.w;

    const float* h0 = (const float*)&h0v;
    const float* ha = (const float*)&hav;
    const float* hb = (const float*)&hbv;
    const float* hc = (const float*)&hcv;
    const float* w0 = (const float*)&w0v;
    const float* w1 = (const float*)&w1v;
    const float* w2 = (const float*)&w2v;
    const float* w3 = (const float*)&w3v;
    const float* w4 = (const float*)&w4v;

    float r0[4], o1o0[4], o1o1[4], o1o2[4], o1e0[4], o1e1[4], o1e2[4];

    #pragma unroll
    for (int j = 0; j < 4; j++) {
        float H0 = h0[j];
        float A = ha[j], B = hb[j], C = hc[j];   // h1[0..2]
        float dot = A * y1x + B * y1y + C * y1z;

        r0[j]   = w0[j] * H0 * y0 + w3[j] * (INV_SQRT3f * dot);

        o1o0[j] = w1[j] * H0 * y1x + w2[j] * A * y0;
        o1o1[j] = w1[j] * H0 * y1y + w2[j] * B * y0;
        o1o2[j] = w1[j] * H0 * y1z + w2[j] * C * y0;

        float cr0 = B * y1z - C * y1y;
        float cr1 = C * y1x - A * y1z;
        float cr2 = A * y1y - B * y1x;
        o1e0[j] = w4[j] * (INV_SQRT2f * cr0);
        o1e1[j] = w4[j] * (INV_SQRT2f * cr1);
        o1e2[j] = w4[j] * (INV_SQRT2f * cr2);
    }

    // write the message into this edge's SMEM row (contiguous 128B per segment
    // across the 8 lanes -> conflict-free STS.128)
    float4* bp = (float4*)(buf + ein * OUT_DIM);
    bp[t]      = make_float4(r0[0],   r0[1],   r0[2],   r0[3]);
    bp[8  + t] = make_float4(o1o0[0], o1o0[1], o1o0[2], o1o0[3]);
    bp[16 + t] = make_float4(o1o1[0], o1o1[1], o1o1[2], o1o1[3]);
    bp[24 + t] = make_float4(o1o2[0], o1o2[1], o1o2[2], o1o2[3]);
    bp[32 + t] = make_float4(o1e0[0], o1e0[1], o1e0[2], o1e0[3]);
    bp[40 + t] = make_float4(o1e1[0], o1e1[1], o1e1[2], o1e1[3]);
    bp[48 + t] = make_float4(o1e2[0], o1e2[1], o1e2[2], o1e2[3]);

    // make the warp's SMEM writes visible to the async proxy; warp-local sync only
    asm volatile("fence.proxy.async.shared::cta;" ::: "memory");
    __syncwarp();

    // one lane per edge issues the 896B bulk reduce-add to the dst row
    if (t == 0) {
        uint32_t saddr = smem_u32(buf + ein * OUT_DIM);
        float* gaddr = out + (long long)dst * OUT_DIM;
        asm volatile(
            "cp.reduce.async.bulk.global.shared::cta.bulk_group.add.f32 [%0], [%1], %2;"
            :: "l"(gaddr), "r"(saddr), "n"(OUT_DIM * 4) : "memory");
        asm volatile("cp.async.bulk.commit_group;" ::: "memory");
        asm volatile("cp.async.bulk.wait_group 0;" ::: "memory");
    }
}

extern "C" void kernel_launch(void* const* d_in, const int* in_sizes, int n_in,
                              void* d_out, int out_size) {
    const float* nf  = (const float*)d_in[0];   // node_features
    const float* ang = (const float*)d_in[1];   // edge_angular
    const int*   ei  = (const int*)d_in[2];     // edge_index (int32)
    const float* tw  = (const float*)d_in[3];   // tp_weights
    float* out = (float*)d_out;

    // zero the (poisoned) output — vectorized
    int n4 = out_size / 4;
    int zgrid = (n4 + 255) / 256;
    if (zgrid > 2368) zgrid = 2368;
    zero_out_kernel<<<zgrid, 256>>>((float4*)out, n4);

    // main kernel: 50000 CTAs of 128 threads, 16 edges each (exact cover)
    convtp_kernel<<<N_EDGES / EDGES_PER_CTA, BLOCK>>>(nf, ang, ei, tw, out);
}

// round 14
// speedup vs baseline: 1.4816x; 1.1472x over previous
#include <cuda_runtime.h>
#include <cstdint>

#define N_NODES   50000
#define N_EDGES   800000
#define IN_DIM    128     // 4*MUL
#define W_DIM     160     // 5*MUL
#define OUT_DIM   224     // 7*MUL
#define MUL       32
#define CAP       64      // bucket slots per node (Poisson(16): P(deg>64) ~ 1e-20)

#define INV_SQRT3f 0.57735026918962576451f
#define INV_SQRT2f 0.70710678118654752440f

// scratch
__device__ int  g_cnt[N_NODES];
__device__ int2 g_bk[(size_t)N_NODES * CAP];   // {edge_id, src} — 25.6 MB

__device__ __forceinline__ float ldcs1(const float* p) { return __ldcs(p); }

// k0: zero per-node counters
__global__ void zero_cnt_kernel() {
    int i = blockIdx.x * blockDim.x + threadIdx.x;
    if (i < N_NODES) g_cnt[i] = 0;
}

// k1: scatter (edge_id, src) into dst buckets
__global__ __launch_bounds__(256)
void scatter_kernel(const int* __restrict__ ei) {
    int e = blockIdx.x * blockDim.x + threadIdx.x;
    if (e >= N_EDGES) return;
    int2 se = __ldcs(((const int2*)ei) + e);
    int slot = atomicAdd(&g_cnt[se.y], 1);
    if (slot < CAP) g_bk[(size_t)se.y * CAP + slot] = make_int2(e, se.x);
}

// k2: one WARP per node, one CHANNEL per lane. Per edge: 9 coalesced scalar
// loads + 1 broadcast; (e,src) comes from pre-loaded per-lane bucket regs via
// shfl. 7 accumulators/lane; epilogue = 7 plain coalesced stores. NO atomics.
__global__ __launch_bounds__(256)
void gather_kernel(const float* __restrict__ nf,   // [N_NODES, 128]
                   const float* __restrict__ ang,  // [N_EDGES, 4]
                   const float* __restrict__ tw,   // [N_EDGES, 160]
                   float* __restrict__ out)        // [N_NODES, 224]
{
    int node = (blockIdx.x * blockDim.x + threadIdx.x) >> 5;   // grid exact cover
    int lane = threadIdx.x & 31;
    if (node >= N_NODES) return;

    int deg = g_cnt[node];
    if (deg > CAP) deg = CAP;

    // pre-load bucket entries: lane holds entries lane and 32+lane
    const int2* bp = g_bk + (size_t)node * CAP;
    int2 ea = bp[lane];
    int2 eb = bp[32 + lane];

    float a0 = 0.f, a1 = 0.f, a2 = 0.f, a3 = 0.f, a4 = 0.f, a5 = 0.f, a6 = 0.f;

    #pragma unroll 2
    for (int i = 0; i < deg; i++) {
        int2 sel = (i < 32) ? ea : eb;             // uniform select
        int e   = __shfl_sync(0xffffffffu, sel.x, i & 31);
        int src = __shfl_sync(0xffffffffu, sel.y, i & 31);

        // node features: coalesced 128B per load, L2-resident table
        const float* hrow = nf + (long long)src * IN_DIM + lane;
        float H0 = __ldg(hrow);
        float A  = __ldg(hrow + MUL);
        float B  = __ldg(hrow + 2 * MUL);
        float C  = __ldg(hrow + 3 * MUL);

        // weights: 512MB single-use stream, evict-first; coalesced 128B loads
        const float* wrow = tw + (long long)e * W_DIM + lane;
        float w0 = ldcs1(wrow);
        float w1 = ldcs1(wrow + MUL);
        float w2 = ldcs1(wrow + 2 * MUL);
        float w3 = ldcs1(wrow + 3 * MUL);
        float w4 = ldcs1(wrow + 4 * MUL);

        // angular: 16B broadcast (same address all lanes), small table
        float4 y = __ldg(((const float4*)ang) + e);
        const float y0 = y.x, y1x = y.y, y1y = y.z, y1z = y.w;

        float dot = A * y1x + B * y1y + C * y1z;

        a0 += w0 * H0 * y0 + w3 * (INV_SQRT3f * dot);

        a1 += w1 * H0 * y1x + w2 * A * y0;
        a2 += w1 * H0 * y1y + w2 * B * y0;
        a3 += w1 * H0 * y1z + w2 * C * y0;

        float cr0 = B * y1z - C * y1y;
        float cr1 = C * y1x - A * y1z;
        float cr2 = A * y1y - B * y1x;
        a4 += w4 * (INV_SQRT2f * cr0);
        a5 += w4 * (INV_SQRT2f * cr1);
        a6 += w4 * (INV_SQRT2f * cr2);
    }

    // plain coalesced stores: full 224-float row always written
    // (covers deg==0 nodes; output needs no pre-zeroing kernel)
    float* op = out + (long long)node * OUT_DIM + lane;
    op[0]        = a0;
    op[MUL]      = a1;
    op[2 * MUL]  = a2;
    op[3 * MUL]  = a3;
    op[4 * MUL]  = a4;
    op[5 * MUL]  = a5;
    op[6 * MUL]  = a6;
}

extern "C" void kernel_launch(void* const* d_in, const int* in_sizes, int n_in,
                              void* d_out, int out_size) {
    const float* nf  = (const float*)d_in[0];   // node_features
    const float* ang = (const float*)d_in[1];   // edge_angular
    const int*   ei  = (const int*)d_in[2];     // edge_index (int32)
    const float* tw  = (const float*)d_in[3];   // tp_weights
    float* out = (float*)d_out;

    zero_cnt_kernel<<<(N_NODES + 255) / 256, 256>>>();
    scatter_kernel<<<(N_EDGES + 255) / 256, 256>>>(ei);

    // one warp per node: 50000 warps = 1.6M threads
    long long total = (long long)N_NODES * 32;
    int grid = (int)((total + 255) / 256);      // 6250
    gather_kernel<<<grid, 256>>>(nf, ang, tw, out);
}